// round 16
// baseline (speedup 1.0000x reference)
#include <cuda_runtime.h>
#include <math.h>
#include <stdint.h>

#define BB 16
#define NNX 512
#define CCX 384
#define HHX 6
#define HDX 64
#define FFD 1152
#define BHX (BB*HHX)        // 96
#define MTOK (BB*NNX)       // 8192
#define OUT_ATTN_OFF ((size_t)MTOK*CCX)   // 3145728

// ---------------- device scratch (no dynamic allocation allowed) ----------------
__device__ float g_x[MTOK*CCX];
__device__ float g_q[BHX*NNX*HDX];
__device__ float g_k[BHX*NNX*HDX];
__device__ float g_v[BHX*NNX*HDX];
__device__ float g_qgr[BHX*NNX*HDX];
__device__ float g_kgr[BHX*NNX*HDX];
__device__ float g_qn4[BHX*NNX];
__device__ float g_kn4[BHX*NNX];
__device__ float g_qk[BHX*NNX*NNX];
__device__ float g_dd[BHX*NNX*NNX];
__device__ float g_attnv[MTOK*CCX];
__device__ float g_src1[MTOK*CCX];
__device__ float g_hff[MTOK*FFD];

// ======================= LayerNorm (row of 384, 128 threads) =======================
__global__ void ln_kernel(const float* __restrict__ in, const float* __restrict__ w,
                          const float* __restrict__ b, float* __restrict__ out)
{
    int row = blockIdx.x;
    int t = threadIdx.x;
    const float* p = in + (size_t)row * CCX;
    float v0 = p[t], v1 = p[t + 128], v2 = p[t + 256];
    __shared__ float sh[4];
    float s = v0 + v1 + v2;
#pragma unroll
    for (int o = 16; o; o >>= 1) s += __shfl_xor_sync(0xffffffffu, s, o);
    if ((t & 31) == 0) sh[t >> 5] = s;
    __syncthreads();
    float mu = (sh[0] + sh[1] + sh[2] + sh[3]) * (1.0f / CCX);
    __syncthreads();
    float d0 = v0 - mu, d1 = v1 - mu, d2 = v2 - mu;
    float s2 = d0 * d0 + d1 * d1 + d2 * d2;
#pragma unroll
    for (int o = 16; o; o >>= 1) s2 += __shfl_xor_sync(0xffffffffu, s2, o);
    if ((t & 31) == 0) sh[t >> 5] = s2;
    __syncthreads();
    float var = (sh[0] + sh[1] + sh[2] + sh[3]) * (1.0f / CCX);
    float r = rsqrtf(var + 1e-5f);
    float* q = out + (size_t)row * CCX;
    q[t]       = d0 * r * w[t]       + b[t];
    q[t + 128] = d1 * r * w[t + 128] + b[t + 128];
    q[t + 256] = d2 * r * w[t + 256] + b[t + 256];
}

// ======================= tf32 helpers =======================
__device__ __forceinline__ uint32_t f2tf32(float x) {
    uint32_t r;
    asm("cvt.rna.tf32.f32 %0, %1;" : "=r"(r) : "f"(x));
    return r;
}

__device__ __forceinline__ void mma_tf32(float& d0, float& d1, float& d2, float& d3,
                                         uint32_t a0, uint32_t a1, uint32_t a2, uint32_t a3,
                                         uint32_t b0, uint32_t b1) {
    asm volatile(
        "mma.sync.aligned.m16n8k8.row.col.f32.tf32.tf32.f32 "
        "{%0,%1,%2,%3}, {%4,%5,%6,%7}, {%8,%9}, {%0,%1,%2,%3};\n"
        : "+f"(d0), "+f"(d1), "+f"(d2), "+f"(d3)
        : "r"(a0), "r"(a1), "r"(a2), "r"(a3), "r"(b0), "r"(b1));
}

// ======================= tf32 mma GEMM: C[M,L] = A[M,K] @ W[L,K]^T + bias =======================
// Double-buffered smem (one barrier per k-tile), 2 CTAs/SM.
#define EPI_NONE 0
#define EPI_QKV  1
#define EPI_GELU 2
#define EPI_RESID 3

template<int EPI>
__global__ __launch_bounds__(256, 2)
void mmgemm_abt(const float* __restrict__ A, const float* __restrict__ W,
                const float* __restrict__ bias, const float* __restrict__ resid,
                float* __restrict__ C, int M, int L, int K)
{
    __shared__ uint32_t As[2][128 * 20];
    __shared__ uint32_t Ws[2][128 * 20];
    int m0 = blockIdx.y * 128;
    int l0 = blockIdx.x * 128;
    int t = threadIdx.x;
    int warp = t >> 5, lane = t & 31;
    int g = lane >> 2, tig = lane & 3;
    int wm = warp >> 2, wn = warp & 3;        // warp grid 2 x 4
    int mB = wm * 64, nB = wn * 32;

    float acc[4][4][4];
#pragma unroll
    for (int i = 0; i < 4; i++)
#pragma unroll
        for (int j = 0; j < 4; j++)
#pragma unroll
            for (int v = 0; v < 4; v++) acc[i][j][v] = 0.f;

    int lr = t >> 2;
    int lc = (t & 3) * 4;
    const float* Ap0 = A + (size_t)(m0 + lr) * K + lc;
    const float* Ap1 = A + (size_t)(m0 + 64 + lr) * K + lc;
    const float* Wp0 = W + (size_t)(l0 + lr) * K + lc;
    const float* Wp1 = W + (size_t)(l0 + 64 + lr) * K + lc;

    float4 rA0 = *(const float4*)(Ap0);
    float4 rA1 = *(const float4*)(Ap1);
    float4 rW0 = *(const float4*)(Wp0);
    float4 rW1 = *(const float4*)(Wp1);

    {
        uint32_t* as0 = As[0] + lr * 20 + lc;
        uint32_t* as1 = As[0] + (64 + lr) * 20 + lc;
        uint32_t* ws0 = Ws[0] + lr * 20 + lc;
        uint32_t* ws1 = Ws[0] + (64 + lr) * 20 + lc;
        as0[0] = f2tf32(rA0.x); as0[1] = f2tf32(rA0.y); as0[2] = f2tf32(rA0.z); as0[3] = f2tf32(rA0.w);
        as1[0] = f2tf32(rA1.x); as1[1] = f2tf32(rA1.y); as1[2] = f2tf32(rA1.z); as1[3] = f2tf32(rA1.w);
        ws0[0] = f2tf32(rW0.x); ws0[1] = f2tf32(rW0.y); ws0[2] = f2tf32(rW0.z); ws0[3] = f2tf32(rW0.w);
        ws1[0] = f2tf32(rW1.x); ws1[1] = f2tf32(rW1.y); ws1[2] = f2tf32(rW1.z); ws1[3] = f2tf32(rW1.w);
    }
    __syncthreads();

    int cur = 0;
    for (int kt = 0; kt < K; kt += 16) {
        bool more = (kt + 16 < K);
        if (more) {
            rA0 = *(const float4*)(Ap0 + kt + 16);
            rA1 = *(const float4*)(Ap1 + kt + 16);
            rW0 = *(const float4*)(Wp0 + kt + 16);
            rW1 = *(const float4*)(Wp1 + kt + 16);
        }
        const uint32_t* Ab = As[cur];
        const uint32_t* Wb = Ws[cur];
#pragma unroll
        for (int ks = 0; ks < 16; ks += 8) {
            uint32_t af[4][4], bf[4][2];
#pragma unroll
            for (int i = 0; i < 4; i++) {
                int base = (mB + i * 16 + g) * 20 + ks + tig;
                af[i][0] = Ab[base];
                af[i][1] = Ab[base + 8 * 20];
                af[i][2] = Ab[base + 4];
                af[i][3] = Ab[base + 8 * 20 + 4];
            }
#pragma unroll
            for (int j = 0; j < 4; j++) {
                int base = (nB + j * 8 + g) * 20 + ks + tig;
                bf[j][0] = Wb[base];
                bf[j][1] = Wb[base + 4];
            }
#pragma unroll
            for (int i = 0; i < 4; i++)
#pragma unroll
                for (int j = 0; j < 4; j++)
                    mma_tf32(acc[i][j][0], acc[i][j][1], acc[i][j][2], acc[i][j][3],
                             af[i][0], af[i][1], af[i][2], af[i][3],
                             bf[j][0], bf[j][1]);
        }
        if (more) {
            int nxt = cur ^ 1;
            uint32_t* as0 = As[nxt] + lr * 20 + lc;
            uint32_t* as1 = As[nxt] + (64 + lr) * 20 + lc;
            uint32_t* ws0 = Ws[nxt] + lr * 20 + lc;
            uint32_t* ws1 = Ws[nxt] + (64 + lr) * 20 + lc;
            as0[0] = f2tf32(rA0.x); as0[1] = f2tf32(rA0.y); as0[2] = f2tf32(rA0.z); as0[3] = f2tf32(rA0.w);
            as1[0] = f2tf32(rA1.x); as1[1] = f2tf32(rA1.y); as1[2] = f2tf32(rA1.z); as1[3] = f2tf32(rA1.w);
            ws0[0] = f2tf32(rW0.x); ws0[1] = f2tf32(rW0.y); ws0[2] = f2tf32(rW0.z); ws0[3] = f2tf32(rW0.w);
            ws1[0] = f2tf32(rW1.x); ws1[1] = f2tf32(rW1.y); ws1[2] = f2tf32(rW1.z); ws1[3] = f2tf32(rW1.w);
            __syncthreads();
            cur = nxt;
        }
    }

#pragma unroll
    for (int i = 0; i < 4; i++) {
#pragma unroll
        for (int j = 0; j < 4; j++) {
            int r0 = m0 + mB + i * 16 + g;
            int c0 = l0 + nB + j * 8 + 2 * tig;
            float b0v = bias[c0], b1v = bias[c0 + 1];
#pragma unroll
            for (int half = 0; half < 2; half++) {
                int row = r0 + half * 8;
                float v0 = acc[i][j][half * 2 + 0] + b0v;
                float v1 = acc[i][j][half * 2 + 1] + b1v;
                if (EPI == EPI_NONE) {
                    *(float2*)&C[(size_t)row * L + c0] = make_float2(v0, v1);
                } else if (EPI == EPI_GELU) {
                    v0 = 0.5f * v0 * (1.0f + erff(v0 * 0.70710678118654752f));
                    v1 = 0.5f * v1 * (1.0f + erff(v1 * 0.70710678118654752f));
                    *(float2*)&C[(size_t)row * L + c0] = make_float2(v0, v1);
                } else if (EPI == EPI_RESID) {
                    const float2 rv = *(const float2*)&resid[(size_t)row * L + c0];
                    *(float2*)&C[(size_t)row * L + c0] = make_float2(v0 + rv.x, v1 + rv.y);
                } else { // QKV scatter
#pragma unroll
                    for (int e = 0; e < 2; e++) {
                        int col = c0 + e;
                        float val = (e == 0) ? v0 : v1;
                        int three = col / 384;
                        int rem = col - three * 384;
                        int h = rem >> 6, d = rem & 63;
                        int bb = row >> 9, n = row & 511;
                        float* dst = (three == 0) ? g_q : ((three == 1) ? g_k : g_v);
                        dst[((size_t)(bb * 6 + h) * 512 + n) * 64 + d] = val;
                    }
                }
            }
        }
    }
}

// ======================= batched NT tf32 GEMM (both score GEMMs in ONE launch) =======================
__global__ __launch_bounds__(256, 2)
void bgemm_nt_mma(const float* __restrict__ Q, const float* __restrict__ Km,
                  const float* __restrict__ Qg, const float* __restrict__ Kg,
                  float* __restrict__ Cqk, float* __restrict__ Cdd)
{
    __shared__ uint32_t As[128 * 20];
    __shared__ uint32_t Ws[128 * 20];
    int z = blockIdx.z;
    int bh = (z < BHX) ? z : (z - BHX);
    const float* X = (z < BHX) ? Q : Qg;
    const float* Y = (z < BHX) ? Km : Kg;
    float* C = (z < BHX) ? Cqk : Cdd;
    int m0 = blockIdx.y * 128;
    int n0 = blockIdx.x * 128;
    int t = threadIdx.x;
    int warp = t >> 5, lane = t & 31;
    int g = lane >> 2, tig = lane & 3;
    int wm = warp >> 2, wn = warp & 3;
    int mB = wm * 64, nB = wn * 32;

    const float* Xb = X + (size_t)bh * NNX * HDX;
    const float* Yb = Y + (size_t)bh * NNX * HDX;

    float acc[4][4][4];
#pragma unroll
    for (int i = 0; i < 4; i++)
#pragma unroll
        for (int j = 0; j < 4; j++)
#pragma unroll
            for (int v = 0; v < 4; v++) acc[i][j][v] = 0.f;

    int lr = t >> 2;
    int lc = (t & 3) * 4;
    const float* Ap0 = Xb + (size_t)(m0 + lr) * HDX + lc;
    const float* Ap1 = Xb + (size_t)(m0 + 64 + lr) * HDX + lc;
    const float* Wp0 = Yb + (size_t)(n0 + lr) * HDX + lc;
    const float* Wp1 = Yb + (size_t)(n0 + 64 + lr) * HDX + lc;

    float4 rA0 = *(const float4*)(Ap0);
    float4 rA1 = *(const float4*)(Ap1);
    float4 rW0 = *(const float4*)(Wp0);
    float4 rW1 = *(const float4*)(Wp1);

    for (int kt = 0; kt < HDX; kt += 16) {
        {
            uint32_t* as0 = As + lr * 20 + lc;
            uint32_t* as1 = As + (64 + lr) * 20 + lc;
            uint32_t* ws0 = Ws + lr * 20 + lc;
            uint32_t* ws1 = Ws + (64 + lr) * 20 + lc;
            as0[0] = f2tf32(rA0.x); as0[1] = f2tf32(rA0.y); as0[2] = f2tf32(rA0.z); as0[3] = f2tf32(rA0.w);
            as1[0] = f2tf32(rA1.x); as1[1] = f2tf32(rA1.y); as1[2] = f2tf32(rA1.z); as1[3] = f2tf32(rA1.w);
            ws0[0] = f2tf32(rW0.x); ws0[1] = f2tf32(rW0.y); ws0[2] = f2tf32(rW0.z); ws0[3] = f2tf32(rW0.w);
            ws1[0] = f2tf32(rW1.x); ws1[1] = f2tf32(rW1.y); ws1[2] = f2tf32(rW1.z); ws1[3] = f2tf32(rW1.w);
        }
        __syncthreads();
        if (kt + 16 < HDX) {
            rA0 = *(const float4*)(Ap0 + kt + 16);
            rA1 = *(const float4*)(Ap1 + kt + 16);
            rW0 = *(const float4*)(Wp0 + kt + 16);
            rW1 = *(const float4*)(Wp1 + kt + 16);
        }
#pragma unroll
        for (int ks = 0; ks < 16; ks += 8) {
            uint32_t af[4][4], bf[4][2];
#pragma unroll
            for (int i = 0; i < 4; i++) {
                int base = (mB + i * 16 + g) * 20 + ks + tig;
                af[i][0] = As[base];
                af[i][1] = As[base + 8 * 20];
                af[i][2] = As[base + 4];
                af[i][3] = As[base + 8 * 20 + 4];
            }
#pragma unroll
            for (int j = 0; j < 4; j++) {
                int base = (nB + j * 8 + g) * 20 + ks + tig;
                bf[j][0] = Ws[base];
                bf[j][1] = Ws[base + 4];
            }
#pragma unroll
            for (int i = 0; i < 4; i++)
#pragma unroll
                for (int j = 0; j < 4; j++)
                    mma_tf32(acc[i][j][0], acc[i][j][1], acc[i][j][2], acc[i][j][3],
                             af[i][0], af[i][1], af[i][2], af[i][3],
                             bf[j][0], bf[j][1]);
        }
        __syncthreads();
    }

    float* Cp = C + (size_t)bh * NNX * NNX;
#pragma unroll
    for (int i = 0; i < 4; i++) {
#pragma unroll
        for (int j = 0; j < 4; j++) {
            int r0 = m0 + mB + i * 16 + g;
            int c0 = n0 + nB + j * 8 + 2 * tig;
#pragma unroll
            for (int half = 0; half < 2; half++) {
                int row = r0 + half * 8;
                *(float2*)&Cp[(size_t)row * NNX + c0] =
                    make_float2(acc[i][j][half * 2 + 0], acc[i][j][half * 2 + 1]);
            }
        }
    }
}

// ======================= per-row squared-norms^2 =======================
__global__ void norms_kernel()
{
    int idx = blockIdx.x * 256 + threadIdx.x;
    if (idx >= BHX * NNX) return;
    const float* pq = g_q + (size_t)idx * 64;
    const float* pk = g_k + (size_t)idx * 64;
    float sq = 0.f, sk = 0.f;
#pragma unroll
    for (int d = 0; d < 64; d++) { sq += pq[d] * pq[d]; sk += pk[d] * pk[d]; }
    g_qn4[idx] = sq * sq;
    g_kn4[idx] = sk * sk;
}

// ======================= register-resident PAIRED Householder QR (512x64, reduced Q) =======================
// Pairs of reflectors (j, j+1) are built by the owner warp and applied together by all
// warps using the compact-WY identity s2 = v_{j+1}.a - tau_j*cross*(v_j.a),
// cross = v_{j+1}.v_j  -- algebraically identical to sequential application.
// Halves the barrier count: 128 paired steps total vs 256.
#define VIDX(i) ((i) + ((i) >> 4))
__global__ __launch_bounds__(512, 1)
void qr_kernel3(const float* __restrict__ X0, float* __restrict__ Q0,
                const float* __restrict__ X1, float* __restrict__ Q1)
{
    int bh = blockIdx.x;
    const float* src = (bh < BHX) ? (X0 + (size_t)bh * 512 * 64)
                                  : (X1 + (size_t)(bh - BHX) * 512 * 64);
    float* dst = (bh < BHX) ? (Q0 + (size_t)bh * 512 * 64)
                            : (Q1 + (size_t)(bh - BHX) * 512 * 64);
    int t = threadIdx.x;
    int w = t >> 5, l = t & 31;
    __shared__ float vA[2][544];   // v_even  (v_j forward / v_je backward)
    __shared__ float vB[2][544];   // v_odd   (v_{j+1} forward / v_jo backward)
    __shared__ float tauv[64];
    __shared__ float crossS[2];

    float a[4][16];
#pragma unroll
    for (int r = 0; r < 16; r++) {
        float4 v4 = *(const float4*)(src + (size_t)(16 * l + r) * 64 + 4 * w);
        a[0][r] = v4.x; a[1][r] = v4.y; a[2][r] = v4.z; a[3][r] = v4.w;
    }

    // ---------------- geqrf, paired ----------------
    for (int p = 0; p < 32; p++) {
        int j = 2 * p;              // even
        int j1 = j + 1;
        int jw = j >> 2;
        int jc = j & 3;             // 0 or 2
        float* va = vA[p & 1];
        float* vb = vB[p & 1];
        if (w == jw) {
#pragma unroll
            for (int cc = 0; cc < 4; cc += 2) if (cc == jc) {
                // reflector j from column cc
                float n2 = 0.f, al = 0.f;
#pragma unroll
                for (int r = 0; r < 16; r++) {
                    int i = 16 * l + r;
                    float x = a[cc][r];
                    n2 += (i > j) ? x * x : 0.f;
                    al += (i == j) ? x : 0.f;
                }
#pragma unroll
                for (int o = 16; o; o >>= 1) {
                    n2 += __shfl_xor_sync(0xffffffffu, n2, o);
                    al += __shfl_xor_sync(0xffffffffu, al, o);
                }
                float tau0, sc0;
                if (n2 == 0.f) { tau0 = 0.f; sc0 = 0.f; }
                else {
                    float be = -copysignf(sqrtf(al * al + n2), al);
                    tau0 = (be - al) / be;
                    sc0  = 1.0f / (al - be);
                }
                float vj[16];
#pragma unroll
                for (int r = 0; r < 16; r++) {
                    int i = 16 * l + r;
                    float vv;
                    if (i < j) vv = 0.f;
                    else if (i == j) vv = 1.f;
                    else { vv = a[cc][r] * sc0; a[cc][r] = vv; }
                    vj[r] = vv;
                    va[VIDX(i)] = vv;
                }
                // apply H_j to column cc+1 (rows >= j; row j becomes R garbage, fine)
                float s = 0.f;
#pragma unroll
                for (int r = 0; r < 16; r++) s += vj[r] * a[cc + 1][r];
#pragma unroll
                for (int o = 16; o; o >>= 1) s += __shfl_xor_sync(0xffffffffu, s, o);
                float c1 = tau0 * s;
#pragma unroll
                for (int r = 0; r < 16; r++) a[cc + 1][r] -= c1 * vj[r];
                // reflector j+1 from updated column cc+1 (4-value interleaved reduce)
                float n2b = 0.f, alb = 0.f, cp = 0.f, vjp = 0.f;
#pragma unroll
                for (int r = 0; r < 16; r++) {
                    int i = 16 * l + r;
                    float x = a[cc + 1][r];
                    n2b += (i > j1) ? x * x : 0.f;
                    alb += (i == j1) ? x : 0.f;
                    cp  += (i > j1) ? x * vj[r] : 0.f;
                    vjp += (i == j1) ? vj[r] : 0.f;
                }
#pragma unroll
                for (int o = 16; o; o >>= 1) {
                    n2b += __shfl_xor_sync(0xffffffffu, n2b, o);
                    alb += __shfl_xor_sync(0xffffffffu, alb, o);
                    cp  += __shfl_xor_sync(0xffffffffu, cp, o);
                    vjp += __shfl_xor_sync(0xffffffffu, vjp, o);
                }
                float tau1, sc1;
                if (n2b == 0.f) { tau1 = 0.f; sc1 = 0.f; }
                else {
                    float be = -copysignf(sqrtf(alb * alb + n2b), alb);
                    tau1 = (be - alb) / be;
                    sc1  = 1.0f / (alb - be);
                }
                float cross = vjp + sc1 * cp;
#pragma unroll
                for (int r = 0; r < 16; r++) {
                    int i = 16 * l + r;
                    float vv;
                    if (i < j1) vv = 0.f;
                    else if (i == j1) vv = 1.f;
                    else { vv = a[cc + 1][r] * sc1; a[cc + 1][r] = vv; }
                    vb[VIDX(i)] = vv;
                }
                if (l == 0) { tauv[j] = tau0; tauv[j1] = tau1; crossS[p & 1] = cross; }
            }
        }
        __syncthreads();
        float tau0 = tauv[j], tau1 = tauv[j1], cross = crossS[p & 1];
        if ((4 * w + 3) > j1) {
            float vjr[16], vkr[16];
#pragma unroll
            for (int r = 0; r < 16; r++) { vjr[r] = va[17 * l + r]; vkr[r] = vb[17 * l + r]; }
#pragma unroll
            for (int c = 0; c < 4; c++) {
                int C = 4 * w + c;
                if (C > j1) {
                    float s1 = 0.f, s2 = 0.f;
#pragma unroll
                    for (int r = 0; r < 16; r++) { s1 += vjr[r] * a[c][r]; s2 += vkr[r] * a[c][r]; }
#pragma unroll
                    for (int o = 16; o; o >>= 1) {
                        s1 += __shfl_xor_sync(0xffffffffu, s1, o);
                        s2 += __shfl_xor_sync(0xffffffffu, s2, o);
                    }
                    s2 -= tau0 * cross * s1;
                    float w1 = tau0 * s1, w2 = tau1 * s2;
#pragma unroll
                    for (int r = 0; r < 16; r++) a[c][r] -= w1 * vjr[r] + w2 * vkr[r];
                }
            }
        }
        // no trailing barrier: vA/vB/crossS double-buffered across pair steps
    }
    __syncthreads();

    // ---------------- org2r, paired backward ----------------
    for (int p = 31; p >= 0; p--) {
        int jo = 2 * p + 1;         // odd (applied first)
        int je = 2 * p;             // even
        int jw = jo >> 2;
        int ce = je & 3;            // 0 or 2
        float* va = vA[p & 1];      // v_je
        float* vb = vB[p & 1];      // v_jo
        float crloc = 0.f, vjeo = 0.f;
        if (w == jw) {
#pragma unroll
            for (int cc = 0; cc < 4; cc += 2) if (cc == ce) {
                float cr = 0.f, vp = 0.f;
#pragma unroll
                for (int r = 0; r < 16; r++) {
                    int i = 16 * l + r;
                    float ve = (i < je) ? 0.f : ((i == je) ? 1.f : a[cc][r]);
                    float vo = (i < jo) ? 0.f : ((i == jo) ? 1.f : a[cc + 1][r]);
                    va[VIDX(i)] = ve;
                    vb[VIDX(i)] = vo;
                    cr += (i >= jo) ? ve * vo : 0.f;
                    vp += (i == jo) ? ve : 0.f;
                }
#pragma unroll
                for (int o = 16; o; o >>= 1) {
                    cr += __shfl_xor_sync(0xffffffffu, cr, o);
                    vp += __shfl_xor_sync(0xffffffffu, vp, o);
                }
                crloc = cr; vjeo = vp;
                if (l == 0) crossS[p & 1] = cr;
            }
        }
        __syncthreads();
        float tau_o = tauv[jo], tau_e = tauv[je], cross = crossS[p & 1];
        // apply H_jo then H_je to columns C > jo
        if ((4 * w + 3) > jo) {
            float vjr[16], vkr[16];
#pragma unroll
            for (int r = 0; r < 16; r++) { vjr[r] = va[17 * l + r]; vkr[r] = vb[17 * l + r]; }
#pragma unroll
            for (int c = 0; c < 4; c++) {
                int C = 4 * w + c;
                if (C > jo) {
                    float s2 = 0.f, s1 = 0.f;
#pragma unroll
                    for (int r = 0; r < 16; r++) { s2 += vkr[r] * a[c][r]; s1 += vjr[r] * a[c][r]; }
#pragma unroll
                    for (int o = 16; o; o >>= 1) {
                        s2 += __shfl_xor_sync(0xffffffffu, s2, o);
                        s1 += __shfl_xor_sync(0xffffffffu, s1, o);
                    }
                    s1 -= tau_o * cross * s2;
                    float w2 = tau_o * s2, w1 = tau_e * s1;
#pragma unroll
                    for (int r = 0; r < 16; r++) a[c][r] -= w2 * vkr[r] + w1 * vjr[r];
                }
            }
        }
        // owner: convert column jo (then apply H_je to it via closed form), convert column je
        if (w == jw) {
#pragma unroll
            for (int cc = 0; cc < 4; cc += 2) if (cc == ce) {
                float vjer[16], vjor[16];
#pragma unroll
                for (int r = 0; r < 16; r++) { vjer[r] = va[17 * l + r]; vjor[r] = vb[17 * l + r]; }
                float s = vjeo - tau_o * crloc;   // = v_je . col_jo (closed form)
                float we = tau_e * s;
#pragma unroll
                for (int r = 0; r < 16; r++) {
                    int i = 16 * l + r;
                    float col;
                    if (i < jo) col = 0.f;
                    else if (i == jo) col = 1.f - tau_o;
                    else col = -tau_o * vjor[r];
                    col -= we * vjer[r];
                    a[cc + 1][r] = col;
                }
#pragma unroll
                for (int r = 0; r < 16; r++) {
                    int i = 16 * l + r;
                    float val;
                    if (i < je) val = 0.f;
                    else if (i == je) val = 1.f - tau_e;
                    else val = -tau_e * vjer[r];
                    a[cc][r] = val;
                }
            }
        }
        // no trailing barrier (double-buffered)
    }
    __syncthreads();

#pragma unroll
    for (int r = 0; r < 16; r++) {
        float4 v4 = make_float4(a[0][r], a[1][r], a[2][r], a[3][r]);
        *(float4*)(dst + (size_t)(16 * l + r) * 64 + 4 * w) = v4;
    }
}

// ======================= fused 18->6 channel mix + softmax (single-pass reductions) =======================
__global__ __launch_bounds__(512)
void mix_softmax(const float* __restrict__ scale_p, const float* __restrict__ rs_p,
                 const float* __restrict__ gs_p, const float* __restrict__ conv_w,
                 const float* __restrict__ conv_b, float* __restrict__ attn_out)
{
    int bn = blockIdx.x;
    int b = bn >> 9, n = bn & 511;
    int t = threadIdx.x;
    __shared__ float cw[108], cb[6], sq4[6], sca[3];
    __shared__ float red[6 * 16];
    __shared__ float gmax[6], gsum[6];
    if (t < 108) cw[t] = conv_w[t];
    if (t < 6) { cb[t] = conv_b[t]; sq4[t] = g_qn4[(b * 6 + t) * 512 + n]; }
    if (t == 120) sca[0] = scale_p[0];
    if (t == 121) sca[1] = rs_p[0];
    if (t == 122) sca[2] = gs_p[0];
    __syncthreads();

    float mix[6];
#pragma unroll
    for (int o = 0; o < 6; o++) mix[o] = cb[o];
#pragma unroll
    for (int h = 0; h < 6; h++) {
        size_t base = ((size_t)(b * 6 + h) * 512 + n) * 512 + t;
        float qk = g_qk[base];
        float dd = g_dd[base];
        float kn4 = g_kn4[(b * 6 + h) * 512 + t];
        float eu = qk * sca[0];
        float ri = sqrtf(fmaxf(sq4[h] + kn4 - 2.0f * qk * qk, 0.0f)) * sca[1];
        float gr = dd * dd * sca[2];
#pragma unroll
        for (int o = 0; o < 6; o++)
            mix[o] += cw[o * 18 + h] * eu + cw[o * 18 + 6 + h] * ri + cw[o * 18 + 12 + h] * gr;
    }

    int lane = t & 31, wid = t >> 5;

#pragma unroll
    for (int o = 0; o < 6; o++) {
        float v = mix[o];
#pragma unroll
        for (int of = 16; of; of >>= 1) v = fmaxf(v, __shfl_xor_sync(0xffffffffu, v, of));
        if (lane == 0) red[o * 16 + wid] = v;
    }
    __syncthreads();
    if (t < 96) {
        int o = t >> 4, idx = t & 15;
        float x = red[o * 16 + idx];
#pragma unroll
        for (int of = 8; of; of >>= 1) x = fmaxf(x, __shfl_xor_sync(0xffffffffu, x, of, 16));
        if (idx == 0) gmax[o] = x;
    }
    __syncthreads();

    float ev[6];
#pragma unroll
    for (int o = 0; o < 6; o++) {
        ev[o] = expf(mix[o] - gmax[o]);
        float s = ev[o];
#pragma unroll
        for (int of = 16; of; of >>= 1) s += __shfl_xor_sync(0xffffffffu, s, of);
        if (lane == 0) red[o * 16 + wid] = s;
    }
    __syncthreads();
    if (t < 96) {
        int o = t >> 4, idx = t & 15;
        float x = red[o * 16 + idx];
#pragma unroll
        for (int of = 8; of; of >>= 1) x += __shfl_xor_sync(0xffffffffu, x, of, 16);
        if (idx == 0) gsum[o] = x;
    }
    __syncthreads();

#pragma unroll
    for (int o = 0; o < 6; o++)
        attn_out[((size_t)(b * 6 + o) * 512 + n) * 512 + t] = ev[o] / gsum[o];
}

// ======================= batched attn @ V (tf32 mma), scattered to [B,N,C] =======================
__global__ __launch_bounds__(256, 2)
void bgemm_av_mma(const float* __restrict__ attn)
{
    __shared__ uint32_t As[128 * 20];
    __shared__ uint32_t Vs[64 * 20];
    int bh = blockIdx.y;
    int m0 = blockIdx.x * 128;
    int b = bh / 6, h = bh - b * 6;
    int t = threadIdx.x;
    int warp = t >> 5, lane = t & 31;
    int g = lane >> 2, tig = lane & 3;
    int wm = warp >> 2, wn = warp & 3;
    int mB = wm * 64, nB = wn * 16;

    const float* Ap = attn + (size_t)bh * NNX * NNX;
    const float* Vp = g_v + (size_t)bh * NNX * HDX;

    float acc[4][2][4];
#pragma unroll
    for (int i = 0; i < 4; i++)
#pragma unroll
        for (int j = 0; j < 2; j++)
#pragma unroll
            for (int v = 0; v < 4; v++) acc[i][j][v] = 0.f;

    int lr = t >> 2;
    int lc = (t & 3) * 4;
    const float* Ap0 = Ap + (size_t)(m0 + lr) * NNX + lc;
    const float* Ap1 = Ap + (size_t)(m0 + 64 + lr) * NNX + lc;
    int vk0 = t >> 6, vn = t & 63;

    float4 rA0 = *(const float4*)(Ap0);
    float4 rA1 = *(const float4*)(Ap1);
    float rV[4];
#pragma unroll
    for (int u = 0; u < 4; u++)
        rV[u] = Vp[(size_t)(vk0 + u * 4) * HDX + vn];

    for (int kt = 0; kt < NNX; kt += 16) {
        {
            uint32_t* as0 = As + lr * 20 + lc;
            uint32_t* as1 = As + (64 + lr) * 20 + lc;
            as0[0] = f2tf32(rA0.x); as0[1] = f2tf32(rA0.y); as0[2] = f2tf32(rA0.z); as0[3] = f2tf32(rA0.w);
            as1[0] = f2tf32(rA1.x); as1[1] = f2tf32(rA1.y); as1[2] = f2tf32(rA1.z); as1[3] = f2tf32(rA1.w);
#pragma unroll
            for (int u = 0; u < 4; u++)
                Vs[vn * 20 + vk0 + u * 4] = f2tf32(rV[u]);
        }
        __syncthreads();
        if (kt + 16 < NNX) {
            rA0 = *(const float4*)(Ap0 + kt + 16);
            rA1 = *(const float4*)(Ap1 + kt + 16);
#pragma unroll
            for (int u = 0; u < 4; u++)
                rV[u] = Vp[(size_t)(kt + 16 + vk0 + u * 4) * HDX + vn];
        }
#pragma unroll
        for (int ks = 0; ks < 16; ks += 8) {
            uint32_t af[4][4], bf[2][2];
#pragma unroll
            for (int i = 0; i < 4; i++) {
                int base = (mB + i * 16 + g) * 20 + ks + tig;
                af[i][0] = As[base];
                af[i][1] = As[base + 8 * 20];
                af[i][2] = As[base + 4];
                af[i][3] = As[base + 8 * 20 + 4];
            }
#pragma unroll
            for (int j = 0; j < 2; j++) {
                int base = (nB + j * 8 + g) * 20 + ks + tig;
                bf[j][0] = Vs[base];
                bf[j][1] = Vs[base + 4];
            }
#pragma unroll
            for (int i = 0; i < 4; i++)
#pragma unroll
                for (int j = 0; j < 2; j++)
                    mma_tf32(acc[i][j][0], acc[i][j][1], acc[i][j][2], acc[i][j][3],
                             af[i][0], af[i][1], af[i][2], af[i][3],
                             bf[j][0], bf[j][1]);
        }
        __syncthreads();
    }

#pragma unroll
    for (int i = 0; i < 4; i++) {
#pragma unroll
        for (int j = 0; j < 2; j++) {
            int r0 = m0 + mB + i * 16 + g;
            int c0 = nB + j * 8 + 2 * tig;
#pragma unroll
            for (int half = 0; half < 2; half++) {
                int m = r0 + half * 8;
                *(float2*)&g_attnv[(size_t)(b * 512 + m) * CCX + h * 64 + c0] =
                    make_float2(acc[i][j][half * 2 + 0], acc[i][j][half * 2 + 1]);
            }
        }
    }
}

// ======================= launch =======================
extern "C" void kernel_launch(void* const* d_in, const int* in_sizes, int n_in,
                              void* d_out, int out_size)
{
    const float* src    = (const float*)d_in[0];
    const float* pre_w  = (const float*)d_in[1];
    const float* pre_b  = (const float*)d_in[2];
    const float* qkv_w  = (const float*)d_in[3];
    const float* qkv_b  = (const float*)d_in[4];
    const float* scale  = (const float*)d_in[5];
    const float* riem   = (const float*)d_in[6];
    const float* grass  = (const float*)d_in[7];
    const float* conv_w = (const float*)d_in[8];
    const float* conv_b = (const float*)d_in[9];
    const float* proj_w = (const float*)d_in[10];
    const float* proj_b = (const float*)d_in[11];
    const float* n1_w   = (const float*)d_in[12];
    const float* n1_b   = (const float*)d_in[13];
    const float* l1_w   = (const float*)d_in[14];
    const float* l1_b   = (const float*)d_in[15];
    const float* l2_w   = (const float*)d_in[16];
    const float* l2_b   = (const float*)d_in[17];
    float* out = (float*)d_out;

    void *p_x, *p_q, *p_k, *p_qgr, *p_kgr, *p_qk, *p_dd, *p_attnv, *p_src1, *p_hff;
    cudaGetSymbolAddress(&p_x, g_x);
    cudaGetSymbolAddress(&p_q, g_q);
    cudaGetSymbolAddress(&p_k, g_k);
    cudaGetSymbolAddress(&p_qgr, g_qgr);
    cudaGetSymbolAddress(&p_kgr, g_kgr);
    cudaGetSymbolAddress(&p_qk, g_qk);
    cudaGetSymbolAddress(&p_dd, g_dd);
    cudaGetSymbolAddress(&p_attnv, g_attnv);
    cudaGetSymbolAddress(&p_src1, g_src1);
    cudaGetSymbolAddress(&p_hff, g_hff);

    // 1. pre-LN
    ln_kernel<<<MTOK, 128>>>(src, pre_w, pre_b, (float*)p_x);
    // 2. QKV projection (tf32 mma), scattered into per-head q/k/v
    mmgemm_abt<EPI_QKV><<<dim3(FFD / 128, MTOK / 128), 256>>>(
        (const float*)p_x, qkv_w, qkv_b, nullptr, nullptr, MTOK, FFD, CCX);
    // 3. row norms^4
    norms_kernel<<<(BHX * NNX + 255) / 256, 256>>>();
    // 4. paired-Householder QR, q and k in one launch (192 blocks)
    qr_kernel3<<<2 * BHX, 512>>>((const float*)p_q, (float*)p_qgr,
                                 (const float*)p_k, (float*)p_kgr);
    // 5. BOTH score GEMMs in one launch (tf32 mma, 2 CTAs/SM)
    bgemm_nt_mma<<<dim3(4, 4, 2 * BHX), 256>>>(
        (const float*)p_q, (const float*)p_k, (const float*)p_qgr, (const float*)p_kgr,
        (float*)p_qk, (float*)p_dd);
    // 6. fused channel-mix + softmax -> attn output region of d_out
    float* attn_out = out + OUT_ATTN_OFF;
    mix_softmax<<<MTOK, 512>>>(scale, riem, grass, conv_w, conv_b, attn_out);
    // 7. attn @ V (tf32 mma) -> [B,N,C] layout
    bgemm_av_mma<<<dim3(4, BHX), 256>>>(attn_out);
    // 8. output projection + residual with original src (tf32 mma)
    mmgemm_abt<EPI_RESID><<<dim3(CCX / 128, MTOK / 128), 256>>>(
        (const float*)p_attnv, proj_w, proj_b, src, (float*)p_src1, MTOK, CCX, CCX);
    // 9. norm1
    ln_kernel<<<MTOK, 128>>>((const float*)p_src1, n1_w, n1_b, (float*)p_x);
    // 10. FF lin1 + exact GELU (tf32 mma)
    mmgemm_abt<EPI_GELU><<<dim3(FFD / 128, MTOK / 128), 256>>>(
        (const float*)p_x, l1_w, l1_b, nullptr, (float*)p_hff, MTOK, FFD, CCX);
    // 11. FF lin2 + residual -> src part of d_out (tf32 mma)
    mmgemm_abt<EPI_RESID><<<dim3(CCX / 128, MTOK / 128), 256>>>(
        (const float*)p_hff, l2_w, l2_b, (const float*)p_x, out, MTOK, CCX, FFD);

    (void)in_sizes; (void)n_in; (void)out_size;
}

// round 17
// speedup vs baseline: 1.0532x; 1.0532x over previous
#include <cuda_runtime.h>
#include <math.h>
#include <stdint.h>

#define BB 16
#define NNX 512
#define CCX 384
#define HHX 6
#define HDX 64
#define FFD 1152
#define BHX (BB*HHX)        // 96
#define MTOK (BB*NNX)       // 8192
#define OUT_ATTN_OFF ((size_t)MTOK*CCX)   // 3145728

// ---------------- device scratch (no dynamic allocation allowed) ----------------
__device__ float g_x[MTOK*CCX];
__device__ float g_q[BHX*NNX*HDX];
__device__ float g_k[BHX*NNX*HDX];
__device__ float g_v[BHX*NNX*HDX];
__device__ float g_qgr[BHX*NNX*HDX];
__device__ float g_kgr[BHX*NNX*HDX];
__device__ float g_qn4[BHX*NNX];
__device__ float g_kn4[BHX*NNX];
__device__ float g_qk[BHX*NNX*NNX];
__device__ float g_dd[BHX*NNX*NNX];
__device__ float g_attnv[MTOK*CCX];
__device__ float g_src1[MTOK*CCX];
__device__ float g_hff[MTOK*FFD];

// ======================= LayerNorm (row of 384, 128 threads) =======================
__global__ void ln_kernel(const float* __restrict__ in, const float* __restrict__ w,
                          const float* __restrict__ b, float* __restrict__ out)
{
    int row = blockIdx.x;
    int t = threadIdx.x;
    const float* p = in + (size_t)row * CCX;
    float v0 = p[t], v1 = p[t + 128], v2 = p[t + 256];
    __shared__ float sh[4];
    float s = v0 + v1 + v2;
#pragma unroll
    for (int o = 16; o; o >>= 1) s += __shfl_xor_sync(0xffffffffu, s, o);
    if ((t & 31) == 0) sh[t >> 5] = s;
    __syncthreads();
    float mu = (sh[0] + sh[1] + sh[2] + sh[3]) * (1.0f / CCX);
    __syncthreads();
    float d0 = v0 - mu, d1 = v1 - mu, d2 = v2 - mu;
    float s2 = d0 * d0 + d1 * d1 + d2 * d2;
#pragma unroll
    for (int o = 16; o; o >>= 1) s2 += __shfl_xor_sync(0xffffffffu, s2, o);
    if ((t & 31) == 0) sh[t >> 5] = s2;
    __syncthreads();
    float var = (sh[0] + sh[1] + sh[2] + sh[3]) * (1.0f / CCX);
    float r = rsqrtf(var + 1e-5f);
    float* q = out + (size_t)row * CCX;
    q[t]       = d0 * r * w[t]       + b[t];
    q[t + 128] = d1 * r * w[t + 128] + b[t + 128];
    q[t + 256] = d2 * r * w[t + 256] + b[t + 256];
}

// ======================= tf32 helpers =======================
__device__ __forceinline__ uint32_t f2tf32(float x) {
    uint32_t r;
    asm("cvt.rna.tf32.f32 %0, %1;" : "=r"(r) : "f"(x));
    return r;
}

__device__ __forceinline__ void mma_tf32(float& d0, float& d1, float& d2, float& d3,
                                         uint32_t a0, uint32_t a1, uint32_t a2, uint32_t a3,
                                         uint32_t b0, uint32_t b1) {
    asm volatile(
        "mma.sync.aligned.m16n8k8.row.col.f32.tf32.tf32.f32 "
        "{%0,%1,%2,%3}, {%4,%5,%6,%7}, {%8,%9}, {%0,%1,%2,%3};\n"
        : "+f"(d0), "+f"(d1), "+f"(d2), "+f"(d3)
        : "r"(a0), "r"(a1), "r"(a2), "r"(a3), "r"(b0), "r"(b1));
}

// ======================= tf32 mma GEMM: C[M,L] = A[M,K] @ W[L,K]^T + bias =======================
// Double-buffered smem (one barrier per k-tile), 2 CTAs/SM.
#define EPI_NONE 0
#define EPI_QKV  1
#define EPI_GELU 2
#define EPI_RESID 3

template<int EPI>
__global__ __launch_bounds__(256, 2)
void mmgemm_abt(const float* __restrict__ A, const float* __restrict__ W,
                const float* __restrict__ bias, const float* __restrict__ resid,
                float* __restrict__ C, int M, int L, int K)
{
    __shared__ uint32_t As[2][128 * 20];
    __shared__ uint32_t Ws[2][128 * 20];
    int m0 = blockIdx.y * 128;
    int l0 = blockIdx.x * 128;
    int t = threadIdx.x;
    int warp = t >> 5, lane = t & 31;
    int g = lane >> 2, tig = lane & 3;
    int wm = warp >> 2, wn = warp & 3;        // warp grid 2 x 4
    int mB = wm * 64, nB = wn * 32;

    float acc[4][4][4];
#pragma unroll
    for (int i = 0; i < 4; i++)
#pragma unroll
        for (int j = 0; j < 4; j++)
#pragma unroll
            for (int v = 0; v < 4; v++) acc[i][j][v] = 0.f;

    int lr = t >> 2;
    int lc = (t & 3) * 4;
    const float* Ap0 = A + (size_t)(m0 + lr) * K + lc;
    const float* Ap1 = A + (size_t)(m0 + 64 + lr) * K + lc;
    const float* Wp0 = W + (size_t)(l0 + lr) * K + lc;
    const float* Wp1 = W + (size_t)(l0 + 64 + lr) * K + lc;

    float4 rA0 = *(const float4*)(Ap0);
    float4 rA1 = *(const float4*)(Ap1);
    float4 rW0 = *(const float4*)(Wp0);
    float4 rW1 = *(const float4*)(Wp1);

    {
        uint32_t* as0 = As[0] + lr * 20 + lc;
        uint32_t* as1 = As[0] + (64 + lr) * 20 + lc;
        uint32_t* ws0 = Ws[0] + lr * 20 + lc;
        uint32_t* ws1 = Ws[0] + (64 + lr) * 20 + lc;
        as0[0] = f2tf32(rA0.x); as0[1] = f2tf32(rA0.y); as0[2] = f2tf32(rA0.z); as0[3] = f2tf32(rA0.w);
        as1[0] = f2tf32(rA1.x); as1[1] = f2tf32(rA1.y); as1[2] = f2tf32(rA1.z); as1[3] = f2tf32(rA1.w);
        ws0[0] = f2tf32(rW0.x); ws0[1] = f2tf32(rW0.y); ws0[2] = f2tf32(rW0.z); ws0[3] = f2tf32(rW0.w);
        ws1[0] = f2tf32(rW1.x); ws1[1] = f2tf32(rW1.y); ws1[2] = f2tf32(rW1.z); ws1[3] = f2tf32(rW1.w);
    }
    __syncthreads();

    int cur = 0;
    for (int kt = 0; kt < K; kt += 16) {
        bool more = (kt + 16 < K);
        if (more) {
            rA0 = *(const float4*)(Ap0 + kt + 16);
            rA1 = *(const float4*)(Ap1 + kt + 16);
            rW0 = *(const float4*)(Wp0 + kt + 16);
            rW1 = *(const float4*)(Wp1 + kt + 16);
        }
        const uint32_t* Ab = As[cur];
        const uint32_t* Wb = Ws[cur];
#pragma unroll
        for (int ks = 0; ks < 16; ks += 8) {
            uint32_t af[4][4], bf[4][2];
#pragma unroll
            for (int i = 0; i < 4; i++) {
                int base = (mB + i * 16 + g) * 20 + ks + tig;
                af[i][0] = Ab[base];
                af[i][1] = Ab[base + 8 * 20];
                af[i][2] = Ab[base + 4];
                af[i][3] = Ab[base + 8 * 20 + 4];
            }
#pragma unroll
            for (int j = 0; j < 4; j++) {
                int base = (nB + j * 8 + g) * 20 + ks + tig;
                bf[j][0] = Wb[base];
                bf[j][1] = Wb[base + 4];
            }
#pragma unroll
            for (int i = 0; i < 4; i++)
#pragma unroll
                for (int j = 0; j < 4; j++)
                    mma_tf32(acc[i][j][0], acc[i][j][1], acc[i][j][2], acc[i][j][3],
                             af[i][0], af[i][1], af[i][2], af[i][3],
                             bf[j][0], bf[j][1]);
        }
        if (more) {
            int nxt = cur ^ 1;
            uint32_t* as0 = As[nxt] + lr * 20 + lc;
            uint32_t* as1 = As[nxt] + (64 + lr) * 20 + lc;
            uint32_t* ws0 = Ws[nxt] + lr * 20 + lc;
            uint32_t* ws1 = Ws[nxt] + (64 + lr) * 20 + lc;
            as0[0] = f2tf32(rA0.x); as0[1] = f2tf32(rA0.y); as0[2] = f2tf32(rA0.z); as0[3] = f2tf32(rA0.w);
            as1[0] = f2tf32(rA1.x); as1[1] = f2tf32(rA1.y); as1[2] = f2tf32(rA1.z); as1[3] = f2tf32(rA1.w);
            ws0[0] = f2tf32(rW0.x); ws0[1] = f2tf32(rW0.y); ws0[2] = f2tf32(rW0.z); ws0[3] = f2tf32(rW0.w);
            ws1[0] = f2tf32(rW1.x); ws1[1] = f2tf32(rW1.y); ws1[2] = f2tf32(rW1.z); ws1[3] = f2tf32(rW1.w);
            __syncthreads();
            cur = nxt;
        }
    }

#pragma unroll
    for (int i = 0; i < 4; i++) {
#pragma unroll
        for (int j = 0; j < 4; j++) {
            int r0 = m0 + mB + i * 16 + g;
            int c0 = l0 + nB + j * 8 + 2 * tig;
            float b0v = bias[c0], b1v = bias[c0 + 1];
#pragma unroll
            for (int half = 0; half < 2; half++) {
                int row = r0 + half * 8;
                float v0 = acc[i][j][half * 2 + 0] + b0v;
                float v1 = acc[i][j][half * 2 + 1] + b1v;
                if (EPI == EPI_NONE) {
                    *(float2*)&C[(size_t)row * L + c0] = make_float2(v0, v1);
                } else if (EPI == EPI_GELU) {
                    v0 = 0.5f * v0 * (1.0f + erff(v0 * 0.70710678118654752f));
                    v1 = 0.5f * v1 * (1.0f + erff(v1 * 0.70710678118654752f));
                    *(float2*)&C[(size_t)row * L + c0] = make_float2(v0, v1);
                } else if (EPI == EPI_RESID) {
                    const float2 rv = *(const float2*)&resid[(size_t)row * L + c0];
                    *(float2*)&C[(size_t)row * L + c0] = make_float2(v0 + rv.x, v1 + rv.y);
                } else { // QKV scatter
#pragma unroll
                    for (int e = 0; e < 2; e++) {
                        int col = c0 + e;
                        float val = (e == 0) ? v0 : v1;
                        int three = col / 384;
                        int rem = col - three * 384;
                        int h = rem >> 6, d = rem & 63;
                        int bb = row >> 9, n = row & 511;
                        float* dst = (three == 0) ? g_q : ((three == 1) ? g_k : g_v);
                        dst[((size_t)(bb * 6 + h) * 512 + n) * 64 + d] = val;
                    }
                }
            }
        }
    }
}

// ======================= batched NT tf32 GEMM tile body (256 threads) =======================
// Computes C[bh][m0:m0+128, n0:n0+128] = X[bh] @ Y[bh]^T using caller-provided smem.
__device__ __forceinline__
void nt_tile_body(const float* __restrict__ Xb, const float* __restrict__ Yb,
                  float* __restrict__ Cp, int m0, int n0, int t,
                  uint32_t* As, uint32_t* Ws)
{
    int warp = t >> 5, lane = t & 31;
    int g = lane >> 2, tig = lane & 3;
    int wm = warp >> 2, wn = warp & 3;
    int mB = wm * 64, nB = wn * 32;

    float acc[4][4][4];
#pragma unroll
    for (int i = 0; i < 4; i++)
#pragma unroll
        for (int j = 0; j < 4; j++)
#pragma unroll
            for (int v = 0; v < 4; v++) acc[i][j][v] = 0.f;

    int lr = t >> 2;
    int lc = (t & 3) * 4;
    const float* Ap0 = Xb + (size_t)(m0 + lr) * HDX + lc;
    const float* Ap1 = Xb + (size_t)(m0 + 64 + lr) * HDX + lc;
    const float* Wp0 = Yb + (size_t)(n0 + lr) * HDX + lc;
    const float* Wp1 = Yb + (size_t)(n0 + 64 + lr) * HDX + lc;

    float4 rA0 = *(const float4*)(Ap0);
    float4 rA1 = *(const float4*)(Ap1);
    float4 rW0 = *(const float4*)(Wp0);
    float4 rW1 = *(const float4*)(Wp1);

    for (int kt = 0; kt < HDX; kt += 16) {
        {
            uint32_t* as0 = As + lr * 20 + lc;
            uint32_t* as1 = As + (64 + lr) * 20 + lc;
            uint32_t* ws0 = Ws + lr * 20 + lc;
            uint32_t* ws1 = Ws + (64 + lr) * 20 + lc;
            as0[0] = f2tf32(rA0.x); as0[1] = f2tf32(rA0.y); as0[2] = f2tf32(rA0.z); as0[3] = f2tf32(rA0.w);
            as1[0] = f2tf32(rA1.x); as1[1] = f2tf32(rA1.y); as1[2] = f2tf32(rA1.z); as1[3] = f2tf32(rA1.w);
            ws0[0] = f2tf32(rW0.x); ws0[1] = f2tf32(rW0.y); ws0[2] = f2tf32(rW0.z); ws0[3] = f2tf32(rW0.w);
            ws1[0] = f2tf32(rW1.x); ws1[1] = f2tf32(rW1.y); ws1[2] = f2tf32(rW1.z); ws1[3] = f2tf32(rW1.w);
        }
        __syncthreads();
        if (kt + 16 < HDX) {
            rA0 = *(const float4*)(Ap0 + kt + 16);
            rA1 = *(const float4*)(Ap1 + kt + 16);
            rW0 = *(const float4*)(Wp0 + kt + 16);
            rW1 = *(const float4*)(Wp1 + kt + 16);
        }
#pragma unroll
        for (int ks = 0; ks < 16; ks += 8) {
            uint32_t af[4][4], bf[4][2];
#pragma unroll
            for (int i = 0; i < 4; i++) {
                int base = (mB + i * 16 + g) * 20 + ks + tig;
                af[i][0] = As[base];
                af[i][1] = As[base + 8 * 20];
                af[i][2] = As[base + 4];
                af[i][3] = As[base + 8 * 20 + 4];
            }
#pragma unroll
            for (int j = 0; j < 4; j++) {
                int base = (nB + j * 8 + g) * 20 + ks + tig;
                bf[j][0] = Ws[base];
                bf[j][1] = Ws[base + 4];
            }
#pragma unroll
            for (int i = 0; i < 4; i++)
#pragma unroll
                for (int j = 0; j < 4; j++)
                    mma_tf32(acc[i][j][0], acc[i][j][1], acc[i][j][2], acc[i][j][3],
                             af[i][0], af[i][1], af[i][2], af[i][3],
                             bf[j][0], bf[j][1]);
        }
        __syncthreads();
    }

#pragma unroll
    for (int i = 0; i < 4; i++) {
#pragma unroll
        for (int j = 0; j < 4; j++) {
            int r0 = m0 + mB + i * 16 + g;
            int c0 = n0 + nB + j * 8 + 2 * tig;
#pragma unroll
            for (int half = 0; half < 2; half++) {
                int row = r0 + half * 8;
                *(float2*)&Cp[(size_t)row * NNX + c0] =
                    make_float2(acc[i][j][half * 2 + 0], acc[i][j][half * 2 + 1]);
            }
        }
    }
}

// ======================= batched NT tf32 GEMM launcher (dd after QR) =======================
__global__ __launch_bounds__(256, 2)
void bgemm_nt_mma(const float* __restrict__ X, const float* __restrict__ Y,
                  float* __restrict__ C)
{
    __shared__ uint32_t As[128 * 20];
    __shared__ uint32_t Ws[128 * 20];
    int bh = blockIdx.z;
    nt_tile_body(X + (size_t)bh * NNX * HDX, Y + (size_t)bh * NNX * HDX,
                 C + (size_t)bh * NNX * NNX,
                 blockIdx.y * 128, blockIdx.x * 128, threadIdx.x, As, Ws);
}

// ======================= per-row squared-norms^2 =======================
__global__ void norms_kernel()
{
    int idx = blockIdx.x * 256 + threadIdx.x;
    if (idx >= BHX * NNX) return;
    const float* pq = g_q + (size_t)idx * 64;
    const float* pk = g_k + (size_t)idx * 64;
    float sq = 0.f, sk = 0.f;
#pragma unroll
    for (int d = 0; d < 64; d++) { sq += pq[d] * pq[d]; sk += pk[d] * pk[d]; }
    g_qn4[idx] = sq * sq;
    g_kn4[idx] = sk * sk;
}

// ======================= merged launch: QR (blocks 0..191) + qk score GEMM (blocks 192..959) =======================
// QR: register-resident Householder (round-15 qr_kernel2 body), 512 threads, 1 CTA/SM.
// GEMM blocks: two independent 128x128 qk tiles per CTA (one per 256-thread half);
// both halves execute identical loop structure so __syncthreads aligns.
// qk = q @ k^T does NOT depend on QR output, so these blocks backfill the SMs
// left idle by QR's partial second wave.
#define VIDX(i) ((i) + ((i) >> 4))
__global__ __launch_bounds__(512, 1)
void qr_plus_qk(const float* __restrict__ X0, float* __restrict__ Q0,
                const float* __restrict__ X1, float* __restrict__ Q1,
                float* __restrict__ Cqk)
{
    __shared__ float vsh[2][544];
    __shared__ float tauv[64];
    __shared__ uint32_t As2[2][128 * 20];
    __shared__ uint32_t Ws2[2][128 * 20];

    if (blockIdx.x >= 2 * BHX) {
        // ---------------- qk tile GEMM ----------------
        int gid = blockIdx.x - 2 * BHX;
        int half = threadIdx.x >> 8;          // 0 or 1
        int t = threadIdx.x & 255;
        int tile = gid * 2 + half;            // 0..1535
        int bh = tile >> 4;
        int tp = tile & 15;
        int m0 = (tp >> 2) * 128;
        int n0 = (tp & 3) * 128;
        nt_tile_body(g_q + (size_t)bh * NNX * HDX, g_k + (size_t)bh * NNX * HDX,
                     Cqk + (size_t)bh * NNX * NNX, m0, n0, t, As2[half], Ws2[half]);
        return;
    }

    // ---------------- QR body ----------------
    int bh = blockIdx.x;
    const float* src = (bh < BHX) ? (X0 + (size_t)bh * 512 * 64)
                                  : (X1 + (size_t)(bh - BHX) * 512 * 64);
    float* dst = (bh < BHX) ? (Q0 + (size_t)bh * 512 * 64)
                            : (Q1 + (size_t)(bh - BHX) * 512 * 64);
    int t = threadIdx.x;
    int w = t >> 5, l = t & 31;

    float a[4][16];
#pragma unroll
    for (int r = 0; r < 16; r++) {
        float4 v4 = *(const float4*)(src + (size_t)(16 * l + r) * 64 + 4 * w);
        a[0][r] = v4.x; a[1][r] = v4.y; a[2][r] = v4.z; a[3][r] = v4.w;
    }

    for (int j = 0; j < 64; j++) {
        int jw = j >> 2, jc = j & 3;
        float* vb = vsh[j & 1];
        if (w == jw) {
#pragma unroll
            for (int cc = 0; cc < 4; cc++) if (cc == jc) {
                float n2 = 0.f, al = 0.f;
#pragma unroll
                for (int r = 0; r < 16; r++) {
                    int i = 16 * l + r;
                    float x = a[cc][r];
                    n2 += (i > j) ? x * x : 0.f;
                    al += (i == j) ? x : 0.f;
                }
#pragma unroll
                for (int o = 16; o; o >>= 1) {
                    n2 += __shfl_xor_sync(0xffffffffu, n2, o);
                    al += __shfl_xor_sync(0xffffffffu, al, o);
                }
                float tau, scal;
                if (n2 == 0.f) { tau = 0.f; scal = 0.f; }
                else {
                    float beta = -copysignf(sqrtf(al * al + n2), al);
                    tau  = (beta - al) / beta;
                    scal = 1.0f / (al - beta);
                }
#pragma unroll
                for (int r = 0; r < 16; r++) {
                    int i = 16 * l + r;
                    float vv;
                    if (i < j) vv = 0.f;
                    else if (i == j) vv = 1.f;
                    else { vv = a[cc][r] * scal; a[cc][r] = vv; }
                    vb[VIDX(i)] = vv;
                }
                if (l == 0) tauv[j] = tau;
            }
        }
        __syncthreads();
        float tau = tauv[j];
        if (tau != 0.f && (4 * w + 3) > j) {
            float vr[16];
#pragma unroll
            for (int r = 0; r < 16; r++) vr[r] = vb[17 * l + r];
#pragma unroll
            for (int c = 0; c < 4; c++) {
                int C = 4 * w + c;
                if (C > j) {
                    float s = 0.f;
#pragma unroll
                    for (int r = 0; r < 16; r++) s += vr[r] * a[c][r];
#pragma unroll
                    for (int o = 16; o; o >>= 1) s += __shfl_xor_sync(0xffffffffu, s, o);
                    float wc = tau * s;
#pragma unroll
                    for (int r = 0; r < 16; r++) a[c][r] -= vr[r] * wc;
                }
            }
        }
    }
    __syncthreads();

    for (int j = 63; j >= 0; j--) {
        int jw = j >> 2, jc = j & 3;
        float tau = tauv[j];
        float* vb = vsh[j & 1];
        if (w == jw) {
#pragma unroll
            for (int cc = 0; cc < 4; cc++) if (cc == jc) {
#pragma unroll
                for (int r = 0; r < 16; r++) {
                    int i = 16 * l + r;
                    float vv;
                    if (i < j) vv = 0.f;
                    else if (i == j) vv = 1.f;
                    else vv = a[cc][r];
                    vb[VIDX(i)] = vv;
                }
            }
        }
        __syncthreads();
        if (tau != 0.f && (4 * w + 3) > j) {
            float vr[16];
#pragma unroll
            for (int r = 0; r < 16; r++) vr[r] = vb[17 * l + r];
#pragma unroll
            for (int c = 0; c < 4; c++) {
                int C = 4 * w + c;
                if (C > j) {
                    float s = 0.f;
#pragma unroll
                    for (int r = 0; r < 16; r++) s += vr[r] * a[c][r];
#pragma unroll
                    for (int o = 16; o; o >>= 1) s += __shfl_xor_sync(0xffffffffu, s, o);
                    float wc = tau * s;
#pragma unroll
                    for (int r = 0; r < 16; r++) a[c][r] -= vr[r] * wc;
                }
            }
        }
        if (w == jw) {
#pragma unroll
            for (int cc = 0; cc < 4; cc++) if (cc == jc) {
#pragma unroll
                for (int r = 0; r < 16; r++) {
                    int i = 16 * l + r;
                    float val;
                    if (i < j) val = 0.f;
                    else if (i == j) val = 1.f - tau;
                    else val = -tau * a[cc][r];
                    a[cc][r] = val;
                }
            }
        }
    }
    __syncthreads();

#pragma unroll
    for (int r = 0; r < 16; r++) {
        float4 v4 = make_float4(a[0][r], a[1][r], a[2][r], a[3][r]);
        *(float4*)(dst + (size_t)(16 * l + r) * 64 + 4 * w) = v4;
    }
}

// ======================= fused 18->6 channel mix + softmax (single-pass reductions) =======================
__global__ __launch_bounds__(512)
void mix_softmax(const float* __restrict__ scale_p, const float* __restrict__ rs_p,
                 const float* __restrict__ gs_p, const float* __restrict__ conv_w,
                 const float* __restrict__ conv_b, float* __restrict__ attn_out)
{
    int bn = blockIdx.x;
    int b = bn >> 9, n = bn & 511;
    int t = threadIdx.x;
    __shared__ float cw[108], cb[6], sq4[6], sca[3];
    __shared__ float red[6 * 16];
    __shared__ float gmax[6], gsum[6];
    if (t < 108) cw[t] = conv_w[t];
    if (t < 6) { cb[t] = conv_b[t]; sq4[t] = g_qn4[(b * 6 + t) * 512 + n]; }
    if (t == 120) sca[0] = scale_p[0];
    if (t == 121) sca[1] = rs_p[0];
    if (t == 122) sca[2] = gs_p[0];
    __syncthreads();

    float mix[6];
#pragma unroll
    for (int o = 0; o < 6; o++) mix[o] = cb[o];
#pragma unroll
    for (int h = 0; h < 6; h++) {
        size_t base = ((size_t)(b * 6 + h) * 512 + n) * 512 + t;
        float qk = g_qk[base];
        float dd = g_dd[base];
        float kn4 = g_kn4[(b * 6 + h) * 512 + t];
        float eu = qk * sca[0];
        float ri = sqrtf(fmaxf(sq4[h] + kn4 - 2.0f * qk * qk, 0.0f)) * sca[1];
        float gr = dd * dd * sca[2];
#pragma unroll
        for (int o = 0; o < 6; o++)
            mix[o] += cw[o * 18 + h] * eu + cw[o * 18 + 6 + h] * ri + cw[o * 18 + 12 + h] * gr;
    }

    int lane = t & 31, wid = t >> 5;

#pragma unroll
    for (int o = 0; o < 6; o++) {
        float v = mix[o];
#pragma unroll
        for (int of = 16; of; of >>= 1) v = fmaxf(v, __shfl_xor_sync(0xffffffffu, v, of));
        if (lane == 0) red[o * 16 + wid] = v;
    }
    __syncthreads();
    if (t < 96) {
        int o = t >> 4, idx = t & 15;
        float x = red[o * 16 + idx];
#pragma unroll
        for (int of = 8; of; of >>= 1) x = fmaxf(x, __shfl_xor_sync(0xffffffffu, x, of, 16));
        if (idx == 0) gmax[o] = x;
    }
    __syncthreads();

    float ev[6];
#pragma unroll
    for (int o = 0; o < 6; o++) {
        ev[o] = expf(mix[o] - gmax[o]);
        float s = ev[o];
#pragma unroll
        for (int of = 16; of; of >>= 1) s += __shfl_xor_sync(0xffffffffu, s, of);
        if (lane == 0) red[o * 16 + wid] = s;
    }
    __syncthreads();
    if (t < 96) {
        int o = t >> 4, idx = t & 15;
        float x = red[o * 16 + idx];
#pragma unroll
        for (int of = 8; of; of >>= 1) x += __shfl_xor_sync(0xffffffffu, x, of, 16);
        if (idx == 0) gsum[o] = x;
    }
    __syncthreads();

#pragma unroll
    for (int o = 0; o < 6; o++)
        attn_out[((size_t)(b * 6 + o) * 512 + n) * 512 + t] = ev[o] / gsum[o];
}

// ======================= batched attn @ V (tf32 mma), scattered to [B,N,C] =======================
__global__ __launch_bounds__(256, 2)
void bgemm_av_mma(const float* __restrict__ attn)
{
    __shared__ uint32_t As[128 * 20];
    __shared__ uint32_t Vs[64 * 20];
    int bh = blockIdx.y;
    int m0 = blockIdx.x * 128;
    int b = bh / 6, h = bh - b * 6;
    int t = threadIdx.x;
    int warp = t >> 5, lane = t & 31;
    int g = lane >> 2, tig = lane & 3;
    int wm = warp >> 2, wn = warp & 3;
    int mB = wm * 64, nB = wn * 16;

    const float* Ap = attn + (size_t)bh * NNX * NNX;
    const float* Vp = g_v + (size_t)bh * NNX * HDX;

    float acc[4][2][4];
#pragma unroll
    for (int i = 0; i < 4; i++)
#pragma unroll
        for (int j = 0; j < 2; j++)
#pragma unroll
            for (int v = 0; v < 4; v++) acc[i][j][v] = 0.f;

    int lr = t >> 2;
    int lc = (t & 3) * 4;
    const float* Ap0 = Ap + (size_t)(m0 + lr) * NNX + lc;
    const float* Ap1 = Ap + (size_t)(m0 + 64 + lr) * NNX + lc;
    int vk0 = t >> 6, vn = t & 63;

    float4 rA0 = *(const float4*)(Ap0);
    float4 rA1 = *(const float4*)(Ap1);
    float rV[4];
#pragma unroll
    for (int u = 0; u < 4; u++)
        rV[u] = Vp[(size_t)(vk0 + u * 4) * HDX + vn];

    for (int kt = 0; kt < NNX; kt += 16) {
        {
            uint32_t* as0 = As + lr * 20 + lc;
            uint32_t* as1 = As + (64 + lr) * 20 + lc;
            as0[0] = f2tf32(rA0.x); as0[1] = f2tf32(rA0.y); as0[2] = f2tf32(rA0.z); as0[3] = f2tf32(rA0.w);
            as1[0] = f2tf32(rA1.x); as1[1] = f2tf32(rA1.y); as1[2] = f2tf32(rA1.z); as1[3] = f2tf32(rA1.w);
#pragma unroll
            for (int u = 0; u < 4; u++)
                Vs[vn * 20 + vk0 + u * 4] = f2tf32(rV[u]);
        }
        __syncthreads();
        if (kt + 16 < NNX) {
            rA0 = *(const float4*)(Ap0 + kt + 16);
            rA1 = *(const float4*)(Ap1 + kt + 16);
#pragma unroll
            for (int u = 0; u < 4; u++)
                rV[u] = Vp[(size_t)(kt + 16 + vk0 + u * 4) * HDX + vn];
        }
#pragma unroll
        for (int ks = 0; ks < 16; ks += 8) {
            uint32_t af[4][4], bf[2][2];
#pragma unroll
            for (int i = 0; i < 4; i++) {
                int base = (mB + i * 16 + g) * 20 + ks + tig;
                af[i][0] = As[base];
                af[i][1] = As[base + 8 * 20];
                af[i][2] = As[base + 4];
                af[i][3] = As[base + 8 * 20 + 4];
            }
#pragma unroll
            for (int j = 0; j < 2; j++) {
                int base = (nB + j * 8 + g) * 20 + ks + tig;
                bf[j][0] = Vs[base];
                bf[j][1] = Vs[base + 4];
            }
#pragma unroll
            for (int i = 0; i < 4; i++)
#pragma unroll
                for (int j = 0; j < 2; j++)
                    mma_tf32(acc[i][j][0], acc[i][j][1], acc[i][j][2], acc[i][j][3],
                             af[i][0], af[i][1], af[i][2], af[i][3],
                             bf[j][0], bf[j][1]);
        }
        __syncthreads();
    }

#pragma unroll
    for (int i = 0; i < 4; i++) {
#pragma unroll
        for (int j = 0; j < 2; j++) {
            int r0 = m0 + mB + i * 16 + g;
            int c0 = nB + j * 8 + 2 * tig;
#pragma unroll
            for (int half = 0; half < 2; half++) {
                int m = r0 + half * 8;
                *(float2*)&g_attnv[(size_t)(b * 512 + m) * CCX + h * 64 + c0] =
                    make_float2(acc[i][j][half * 2 + 0], acc[i][j][half * 2 + 1]);
            }
        }
    }
}

// ======================= launch =======================
extern "C" void kernel_launch(void* const* d_in, const int* in_sizes, int n_in,
                              void* d_out, int out_size)
{
    const float* src    = (const float*)d_in[0];
    const float* pre_w  = (const float*)d_in[1];
    const float* pre_b  = (const float*)d_in[2];
    const float* qkv_w  = (const float*)d_in[3];
    const float* qkv_b  = (const float*)d_in[4];
    const float* scale  = (const float*)d_in[5];
    const float* riem   = (const float*)d_in[6];
    const float* grass  = (const float*)d_in[7];
    const float* conv_w = (const float*)d_in[8];
    const float* conv_b = (const float*)d_in[9];
    const float* proj_w = (const float*)d_in[10];
    const float* proj_b = (const float*)d_in[11];
    const float* n1_w   = (const float*)d_in[12];
    const float* n1_b   = (const float*)d_in[13];
    const float* l1_w   = (const float*)d_in[14];
    const float* l1_b   = (const float*)d_in[15];
    const float* l2_w   = (const float*)d_in[16];
    const float* l2_b   = (const float*)d_in[17];
    float* out = (float*)d_out;

    void *p_x, *p_q, *p_k, *p_qgr, *p_kgr, *p_qk, *p_dd, *p_attnv, *p_src1, *p_hff;
    cudaGetSymbolAddress(&p_x, g_x);
    cudaGetSymbolAddress(&p_q, g_q);
    cudaGetSymbolAddress(&p_k, g_k);
    cudaGetSymbolAddress(&p_qgr, g_qgr);
    cudaGetSymbolAddress(&p_kgr, g_kgr);
    cudaGetSymbolAddress(&p_qk, g_qk);
    cudaGetSymbolAddress(&p_dd, g_dd);
    cudaGetSymbolAddress(&p_attnv, g_attnv);
    cudaGetSymbolAddress(&p_src1, g_src1);
    cudaGetSymbolAddress(&p_hff, g_hff);

    // 1. pre-LN
    ln_kernel<<<MTOK, 128>>>(src, pre_w, pre_b, (float*)p_x);
    // 2. QKV projection (tf32 mma), scattered into per-head q/k/v
    mmgemm_abt<EPI_QKV><<<dim3(FFD / 128, MTOK / 128), 256>>>(
        (const float*)p_x, qkv_w, qkv_b, nullptr, nullptr, MTOK, FFD, CCX);
    // 3. row norms^4
    norms_kernel<<<(BHX * NNX + 255) / 256, 256>>>();
    // 4. QR (192 blocks) + qk score GEMM (768 blocks) in ONE launch:
    //    qk tiles backfill the SMs idled by QR's partial second wave.
    qr_plus_qk<<<2 * BHX + 768, 512>>>((const float*)p_q, (float*)p_qgr,
                                       (const float*)p_k, (float*)p_kgr,
                                       (float*)p_qk);
    // 5. dd score GEMM (needs QR output)
    bgemm_nt_mma<<<dim3(4, 4, BHX), 256>>>((const float*)p_qgr, (const float*)p_kgr,
                                           (float*)p_dd);
    // 6. fused channel-mix + softmax -> attn output region of d_out
    float* attn_out = out + OUT_ATTN_OFF;
    mix_softmax<<<MTOK, 512>>>(scale, riem, grass, conv_w, conv_b, attn_out);
    // 7. attn @ V (tf32 mma) -> [B,N,C] layout
    bgemm_av_mma<<<dim3(4, BHX), 256>>>(attn_out);
    // 8. output projection + residual with original src (tf32 mma)
    mmgemm_abt<EPI_RESID><<<dim3(CCX / 128, MTOK / 128), 256>>>(
        (const float*)p_attnv, proj_w, proj_b, src, (float*)p_src1, MTOK, CCX, CCX);
    // 9. norm1
    ln_kernel<<<MTOK, 128>>>((const float*)p_src1, n1_w, n1_b, (float*)p_x);
    // 10. FF lin1 + exact GELU (tf32 mma)
    mmgemm_abt<EPI_GELU><<<dim3(FFD / 128, MTOK / 128), 256>>>(
        (const float*)p_x, l1_w, l1_b, nullptr, (float*)p_hff, MTOK, FFD, CCX);
    // 11. FF lin2 + residual -> src part of d_out (tf32 mma)
    mmgemm_abt<EPI_RESID><<<dim3(CCX / 128, MTOK / 128), 256>>>(
        (const float*)p_hff, l2_w, l2_b, (const float*)p_x, out, MTOK, CCX, FFD);

    (void)in_sizes; (void)n_in; (void)out_size;
}